// round 15
// baseline (speedup 1.0000x reference)
#include <cuda_runtime.h>
#include <cuda_bf16.h>
#include <math.h>
#include <stdint.h>

#define NN  12288
#define NE  393216
#define FIN 256
#define FH  128
#define FZ  64
#define KC  128   // stored Z layout: [hi(64) | lo(64)] per row

// ---------------- scratch (no allocs allowed) ----------------
__device__ int   g_deg[NN];          // zero-initialized; k_scan restores zero each call
__device__ float g_norm[NN];
__device__ int   g_rowptr[NN + 1];
__device__ int   g_cursor[NN];
__device__ int   g_csrc[NE];
__device__ float g_H1[NN * FH];
__device__ float g_hidden[NN * FH];
__device__ float g_MS[NN * FH];
__device__ __align__(16) __nv_bfloat16 g_Zc[NN * KC];
__device__ int   g_is64 = 1;

// ---------------- f32x2 packed-FMA helpers (prologue GEMMs) ----------------
__device__ __forceinline__ unsigned long long ffma2(unsigned long long a,
                                                    unsigned long long b,
                                                    unsigned long long c) {
    unsigned long long d;
    asm("fma.rn.f32x2 %0, %1, %2, %3;" : "=l"(d) : "l"(a), "l"(b), "l"(c));
    return d;
}
__device__ __forceinline__ unsigned long long pack2(float x, float y) {
    unsigned long long d;
    asm("mov.b64 %0, {%1, %2};" : "=l"(d) : "f"(x), "f"(y));
    return d;
}
__device__ __forceinline__ float2 unpack2(unsigned long long v) {
    float2 r;
    asm("mov.b64 {%0, %1}, %2;" : "=f"(r.x), "=f"(r.y) : "l"(v));
    return r;
}

__device__ __forceinline__ uint32_t smem_u32(const void* p) {
    uint32_t a;
    asm("{ .reg .u64 t; cvta.to.shared.u64 t, %1; cvt.u32.u64 %0, t; }" : "=r"(a) : "l"(p));
    return a;
}
#define CP_ASYNC16(dst, src) \
    asm volatile("cp.async.cg.shared.global [%0], [%1], 16;" :: "r"(dst), "l"(src))
#define CP_COMMIT() asm volatile("cp.async.commit_group;" ::: "memory")
#define CP_WAIT(n)  asm volatile("cp.async.wait_group %0;" :: "n"(n) : "memory")

// ---------------- init: dtype detect only (deg zeroing moved into k_scan) ----------------
__global__ void k_init(const int* __restrict__ ei32) {
    int nz = (ei32[threadIdx.x * 2 + 1] != 0);
    unsigned m = __ballot_sync(0xffffffffu, nz);
    if (threadIdx.x == 0) g_is64 = (m == 0) ? 1 : 0;
}

__device__ __forceinline__ int load_idx(const void* ei, int pos) {
    if (g_is64) return (int)((const long long*)ei)[pos];
    return ((const int*)ei)[pos];
}

// 2 edges per thread, vectorized index loads
__global__ void k_count(const void* __restrict__ ei) {
    int t = blockIdx.x * blockDim.x + threadIdx.x;
    int e = t * 2;
    if (e >= NE) return;
    int d0, d1;
    if (g_is64) {
        int4 v = *(const int4*)((const long long*)ei + NE + e);
        d0 = v.x; d1 = v.z;
    } else {
        int2 v = *(const int2*)((const int*)ei + NE + e);
        d0 = v.x; d1 = v.y;
    }
    atomicAdd(&g_deg[d0], 1);
    atomicAdd(&g_deg[d1], 1);
}

__global__ void k_scan() {
    __shared__ int wsum[32];
    int t = threadIdx.x, lane = t & 31, w = t >> 5;
    int warpBase = w * 384;
    int vals[12], excl[12];
#pragma unroll
    for (int k = 0; k < 12; k++) vals[k] = g_deg[warpBase + k * 32 + lane];
    int run = 0;
#pragma unroll
    for (int k = 0; k < 12; k++) {
        int d = vals[k];
        int v = d;
#pragma unroll
        for (int off = 1; off < 32; off <<= 1) {
            int u = __shfl_up_sync(0xffffffffu, v, off);
            if (lane >= off) v += u;
        }
        excl[k] = run + v - d;
        run += __shfl_sync(0xffffffffu, v, 31);
    }
    if (lane == 0) wsum[w] = run;
    __syncthreads();
    if (w == 0) {
        int x = wsum[lane];
#pragma unroll
        for (int off = 1; off < 32; off <<= 1) {
            int u = __shfl_up_sync(0xffffffffu, x, off);
            if (lane >= off) x += u;
        }
        wsum[lane] = x;
    }
    __syncthreads();
    int base = w ? wsum[w - 1] : 0;
#pragma unroll
    for (int k = 0; k < 12; k++) {
        int idx = warpBase + k * 32 + lane;
        int p = base + excl[k];
        g_rowptr[idx] = p;
        g_cursor[idx] = p;
        int d = vals[k];
        g_norm[idx] = rsqrtf((float)(d > 1 ? d : 1));
        g_deg[idx] = 0;  // restore invariant for the next graph replay
    }
    if (t == 1023) g_rowptr[NN] = wsum[31];
}

// 2 edges per thread, vectorized src+dst loads
__global__ void k_fill(const void* __restrict__ ei) {
    int t = blockIdx.x * blockDim.x + threadIdx.x;
    int e = t * 2;
    if (e >= NE) return;
    int s0, s1, d0, d1;
    if (g_is64) {
        int4 vs = *(const int4*)((const long long*)ei + e);
        int4 vd = *(const int4*)((const long long*)ei + NE + e);
        s0 = vs.x; s1 = vs.z; d0 = vd.x; d1 = vd.z;
    } else {
        int2 vs = *(const int2*)((const int*)ei + e);
        int2 vd = *(const int2*)((const int*)ei + NE + e);
        s0 = vs.x; s1 = vs.y; d0 = vd.x; d1 = vd.y;
    }
    g_csrc[atomicAdd(&g_cursor[d0], 1)] = s0;
    g_csrc[atomicAdd(&g_cursor[d1], 1)] = s1;
}

// ---------------- dense GEMM [M,K] x [K,128], FFMA2 ----------------
// MODE 0: C = Ain@Bin (norm folded into k_agg1; independent of CSR chain).
// MODE 1: C = (g_hidden@[Wm|Ws])*norm[row]; Ain=Wm, Bin=Ws read directly.
template <int K, int MODE>
__global__ void __launch_bounds__(256) k_gemm_norm(const float* __restrict__ Ain,
                                                   const float* __restrict__ Bin) {
    __shared__ float As[32][68];
    __shared__ float Bs[32][132];
    const float* A = (MODE == 0) ? Ain : g_hidden;
    float*       C = (MODE == 0) ? g_H1 : g_MS;

    int tid = threadIdx.x;
    int tx = tid & 15, ty = tid >> 4;
    int rowBase = blockIdx.x * 64;

    unsigned long long acc2[4][4];
#pragma unroll
    for (int i = 0; i < 4; i++)
#pragma unroll
        for (int q = 0; q < 4; q++) acc2[i][q] = 0ULL;

    for (int kc = 0; kc < K; kc += 32) {
#pragma unroll
        for (int i = 0; i < 2; i++) {
            int slot = tid + i * 256;
            int r = slot >> 3, c4 = slot & 7;
            float4 v = *(const float4*)&A[(size_t)(rowBase + r) * K + kc + c4 * 4];
            As[c4 * 4 + 0][r] = v.x; As[c4 * 4 + 1][r] = v.y;
            As[c4 * 4 + 2][r] = v.z; As[c4 * 4 + 3][r] = v.w;
        }
#pragma unroll
        for (int i = 0; i < 4; i++) {
            int slot = tid + i * 256;
            int r = slot >> 5, c4 = slot & 31;
            if (MODE == 0) {
                *(float4*)&Bs[r][c4 * 4] = *(const float4*)&Bin[(kc + r) * 128 + c4 * 4];
            } else {
                const float* srcp = (c4 < 16) ? Ain : Bin;
                int jj = (c4 & 15) * 4;
                *(float4*)&Bs[r][c4 * 4] = *(const float4*)&srcp[(kc + r) * 64 + jj];
            }
        }
        __syncthreads();
#pragma unroll
        for (int k = 0; k < 32; k++) {
            float4 av = *(const float4*)&As[k][ty * 4];
            unsigned long long a2[4];
            a2[0] = pack2(av.x, av.x); a2[1] = pack2(av.y, av.y);
            a2[2] = pack2(av.z, av.z); a2[3] = pack2(av.w, av.w);
            unsigned long long b2[4];
#pragma unroll
            for (int q = 0; q < 4; q++)
                b2[q] = *(const unsigned long long*)&Bs[k][tx * 8 + 2 * q];
#pragma unroll
            for (int i = 0; i < 4; i++)
#pragma unroll
                for (int q = 0; q < 4; q++) acc2[i][q] = ffma2(a2[i], b2[q], acc2[i][q]);
        }
        __syncthreads();
    }
#pragma unroll
    for (int i = 0; i < 4; i++) {
        int r = rowBase + ty * 4 + i;
        float nm = (MODE == 0) ? 1.0f : g_norm[r];
        float o[8];
#pragma unroll
        for (int q = 0; q < 4; q++) {
            float2 f = unpack2(acc2[i][q]);
            o[2 * q] = f.x * nm;
            o[2 * q + 1] = f.y * nm;
        }
        float* op = &C[(size_t)r * 128 + tx * 8];
        *(float4*)&op[0] = make_float4(o[0], o[1], o[2], o[3]);
        *(float4*)&op[4] = make_float4(o[4], o[5], o[6], o[7]);
    }
}

// ---------------- gather aggregation (warp per node) ----------------
// acc += H1[src] * norm[src]  (pre-norm folded into the gather)
__global__ void k_agg1() {
    int gw = (blockIdx.x * blockDim.x + threadIdx.x) >> 5;
    if (gw >= NN) return;
    int lane = threadIdx.x & 31;
    int s0 = g_rowptr[gw], s1 = g_rowptr[gw + 1];
    float4 ac0 = make_float4(0.f, 0.f, 0.f, 0.f);
    float4 ac1 = make_float4(0.f, 0.f, 0.f, 0.f);
    int e = s0;
    for (; e + 1 < s1; e += 2) {
        int a = g_csrc[e], b = g_csrc[e + 1];
        float na = g_norm[a], nb = g_norm[b];
        float4 va = *(const float4*)&g_H1[(size_t)a * FH + lane * 4];
        float4 vb = *(const float4*)&g_H1[(size_t)b * FH + lane * 4];
        ac0.x = fmaf(va.x, na, ac0.x); ac0.y = fmaf(va.y, na, ac0.y);
        ac0.z = fmaf(va.z, na, ac0.z); ac0.w = fmaf(va.w, na, ac0.w);
        ac1.x = fmaf(vb.x, nb, ac1.x); ac1.y = fmaf(vb.y, nb, ac1.y);
        ac1.z = fmaf(vb.z, nb, ac1.z); ac1.w = fmaf(vb.w, nb, ac1.w);
    }
    if (e < s1) {
        int a = g_csrc[e];
        float na = g_norm[a];
        float4 va = *(const float4*)&g_H1[(size_t)a * FH + lane * 4];
        ac0.x = fmaf(va.x, na, ac0.x); ac0.y = fmaf(va.y, na, ac0.y);
        ac0.z = fmaf(va.z, na, ac0.z); ac0.w = fmaf(va.w, na, ac0.w);
    }
    float nm = g_norm[gw];
    *(float4*)&g_hidden[(size_t)gw * FH + lane * 4] =
        make_float4((ac0.x + ac1.x) * nm, (ac0.y + ac1.y) * nm,
                    (ac0.z + ac1.z) * nm, (ac0.w + ac1.w) * nm);
}

// aggregate MS, post-norm, relu, reparameterize, emit [hi|lo] bf16 rows
__global__ void k_agg2z(const float* __restrict__ noise) {
    __shared__ float sm[8][128];
    int wl = threadIdx.x >> 5;
    int gw = (blockIdx.x * blockDim.x + threadIdx.x) >> 5;
    if (gw >= NN) return;
    int lane = threadIdx.x & 31;
    int s0 = g_rowptr[gw], s1 = g_rowptr[gw + 1];
    float4 ac0 = make_float4(0.f, 0.f, 0.f, 0.f);
    float4 ac1 = make_float4(0.f, 0.f, 0.f, 0.f);
    int e = s0;
    for (; e + 3 < s1; e += 4) {
        int a = g_csrc[e], b = g_csrc[e + 1], c = g_csrc[e + 2], d = g_csrc[e + 3];
        float4 va = *(const float4*)&g_MS[(size_t)a * FH + lane * 4];
        float4 vb = *(const float4*)&g_MS[(size_t)b * FH + lane * 4];
        float4 vc = *(const float4*)&g_MS[(size_t)c * FH + lane * 4];
        float4 vd = *(const float4*)&g_MS[(size_t)d * FH + lane * 4];
        ac0.x += va.x + vb.x; ac0.y += va.y + vb.y;
        ac0.z += va.z + vb.z; ac0.w += va.w + vb.w;
        ac1.x += vc.x + vd.x; ac1.y += vc.y + vd.y;
        ac1.z += vc.z + vd.z; ac1.w += vc.w + vd.w;
    }
    for (; e < s1; e++) {
        int a = g_csrc[e];
        float4 va = *(const float4*)&g_MS[(size_t)a * FH + lane * 4];
        ac0.x += va.x; ac0.y += va.y; ac0.z += va.z; ac0.w += va.w;
    }
    float nm = g_norm[gw];
    sm[wl][lane * 4 + 0] = fmaxf((ac0.x + ac1.x) * nm, 0.f);
    sm[wl][lane * 4 + 1] = fmaxf((ac0.y + ac1.y) * nm, 0.f);
    sm[wl][lane * 4 + 2] = fmaxf((ac0.z + ac1.z) * nm, 0.f);
    sm[wl][lane * 4 + 3] = fmaxf((ac0.w + ac1.w) * nm, 0.f);
    __syncwarp();
    if (lane < 16) {
        int j = lane * 4;
        float4 nz = *(const float4*)&noise[(size_t)gw * FZ + j];
        float z[4];
        z[0] = fmaf(nz.x, expf(sm[wl][64 + j + 0]), sm[wl][j + 0]);
        z[1] = fmaf(nz.y, expf(sm[wl][64 + j + 1]), sm[wl][j + 1]);
        z[2] = fmaf(nz.z, expf(sm[wl][64 + j + 2]), sm[wl][j + 2]);
        z[3] = fmaf(nz.w, expf(sm[wl][64 + j + 3]), sm[wl][j + 3]);
        __nv_bfloat16 hi[4], lo[4];
#pragma unroll
        for (int q = 0; q < 4; q++) {
            hi[q] = __float2bfloat16(z[q]);
            lo[q] = __float2bfloat16(z[q] - __bfloat162float(hi[q]));
        }
        *(__nv_bfloat162*)&g_Zc[(size_t)gw * KC + j]          = *(__nv_bfloat162*)&hi[0];
        *(__nv_bfloat162*)&g_Zc[(size_t)gw * KC + j + 2]      = *(__nv_bfloat162*)&hi[2];
        *(__nv_bfloat162*)&g_Zc[(size_t)gw * KC + 64 + j]     = *(__nv_bfloat162*)&lo[0];
        *(__nv_bfloat162*)&g_Zc[(size_t)gw * KC + 64 + j + 2] = *(__nv_bfloat162*)&lo[2];
    }
}

// ---------------- Z @ Z^T via mma.sync bf16, split-precision (R12 structure) ----------------
#define ZS 136     // padded smem row stride in bf16 (272 B)
#define NTRI 4656  // 96*97/2 upper-triangle tiles

__device__ __forceinline__ void ldsm_x4(uint32_t addr, uint32_t& r0, uint32_t& r1,
                                        uint32_t& r2, uint32_t& r3) {
    asm volatile("ldmatrix.sync.aligned.m8n8.x4.shared.b16 {%0,%1,%2,%3}, [%4];"
                 : "=r"(r0), "=r"(r1), "=r"(r2), "=r"(r3) : "r"(addr));
}
__device__ __forceinline__ void mma16816(float* d, uint32_t a0, uint32_t a1,
                                         uint32_t a2, uint32_t a3, uint32_t b0,
                                         uint32_t b1) {
    asm volatile(
        "mma.sync.aligned.m16n8k16.row.col.f32.bf16.bf16.f32 "
        "{%0,%1,%2,%3}, {%4,%5,%6,%7}, {%8,%9}, {%0,%1,%2,%3};"
        : "+f"(d[0]), "+f"(d[1]), "+f"(d[2]), "+f"(d[3])
        : "r"(a0), "r"(a1), "r"(a2), "r"(a3), "r"(b0), "r"(b1));
}

__global__ void __launch_bounds__(256, 2) k_zzt_mma(float* __restrict__ out) {
    // triangular decode: row by has (96 - by) tiles, bx in [by, 96)
    int t = blockIdx.x;
    int by = (int)((193.0f - sqrtf(fmaf(-8.0f, (float)t, 193.0f * 193.0f))) * 0.5f);
    while (by * 96 - (by * (by - 1)) / 2 > t) by--;
    while ((by + 1) * 96 - ((by + 1) * by) / 2 <= t) by++;
    const int bx = by + (t - (by * 96 - (by * (by - 1)) / 2));

    extern __shared__ __nv_bfloat16 zs[];  // A: [128][ZS], B: [128][ZS]
    __nv_bfloat16* As = zs;
    __nv_bfloat16* Bs = zs + 128 * ZS;
    const int tid = threadIdx.x;
    const int lane = tid & 31, wid = tid >> 5;
    const int wm = wid & 3, wn = wid >> 2;
    const int rowBase = by * 128;
    const int colBase = bx * 128;

    // group 0: hi halves of A and B
    {
        int tile = tid >> 7, r = tid & 127;
        int grow = (tile ? colBase : rowBase) + r;
        const char* src = (const char*)&g_Zc[(size_t)grow * KC];
        uint32_t dst = smem_u32((tile ? Bs : As) + r * ZS);
#pragma unroll
        for (int i = 0; i < 8; i++) CP_ASYNC16(dst + i * 16, src + i * 16);
    }
    CP_COMMIT();
    // group 1: B.lo
    {
        int r = tid >> 1, h = (tid & 1) * 64;
        const char* src = (const char*)&g_Zc[(size_t)(colBase + r) * KC] + 128 + h;
        uint32_t dst = smem_u32(Bs + r * ZS) + 128 + h;
#pragma unroll
        for (int i = 0; i < 4; i++) CP_ASYNC16(dst + i * 16, src + i * 16);
    }
    CP_COMMIT();
    // group 2: A.lo
    {
        int r = tid >> 1, h = (tid & 1) * 64;
        const char* src = (const char*)&g_Zc[(size_t)(rowBase + r) * KC] + 128 + h;
        uint32_t dst = smem_u32(As + r * ZS) + 128 + h;
#pragma unroll
        for (int i = 0; i < 4; i++) CP_ASYNC16(dst + i * 16, src + i * 16);
    }
    CP_COMMIT();

    uint32_t aBase = smem_u32(As);
    uint32_t bBase = smem_u32(Bs);
    const int lr = lane & 15, lc = (lane >> 4) * 8;

    float acc[2][8][4];
#pragma unroll
    for (int mt = 0; mt < 2; mt++)
#pragma unroll
        for (int nt = 0; nt < 8; nt++)
#pragma unroll
            for (int q = 0; q < 4; q++) acc[mt][nt][q] = 0.f;

    const int ks_a[12] = {0, 1, 2, 3, 0, 1, 2, 3, 4, 5, 6, 7};
    const int ks_b[12] = {0, 1, 2, 3, 4, 5, 6, 7, 0, 1, 2, 3};

    CP_WAIT(2);
    __syncthreads();

#pragma unroll
    for (int ks = 0; ks < 12; ks++) {
        if (ks == 4) { CP_WAIT(1); __syncthreads(); }
        if (ks == 8) { CP_WAIT(0); __syncthreads(); }
        const int ka = ks_a[ks] * 16, kb = ks_b[ks] * 16;
        uint32_t a[2][4];
#pragma unroll
        for (int mt = 0; mt < 2; mt++) {
            uint32_t ad = aBase + ((wm * 32 + mt * 16 + lr) * ZS + ka + lc) * 2;
            ldsm_x4(ad, a[mt][0], a[mt][1], a[mt][2], a[mt][3]);
        }
        uint32_t b[8][2];
#pragma unroll
        for (int np = 0; np < 4; np++) {
            uint32_t bd = bBase + ((wn * 64 + np * 16 + lr) * ZS + kb + lc) * 2;
            uint32_t r0, r1, r2, r3;
            ldsm_x4(bd, r0, r1, r2, r3);
            b[2 * np][0] = r0; b[2 * np][1] = r2;
            b[2 * np + 1][0] = r1; b[2 * np + 1][1] = r3;
        }
#pragma unroll
        for (int mt = 0; mt < 2; mt++)
#pragma unroll
            for (int nt = 0; nt < 8; nt++)
                mma16816(acc[mt][nt], a[mt][0], a[mt][1], a[mt][2], a[mt][3],
                         b[nt][0], b[nt][1]);
    }

    // Epilogue: streaming stores (write-once output; keep L2 for operands).
    const int qr = lane >> 2, qc = (lane & 3) * 2;
    const bool mirror = (bx != by);
#pragma unroll
    for (int mt = 0; mt < 2; mt++) {
        int r0 = rowBase + wm * 32 + mt * 16 + qr;
#pragma unroll
        for (int nt = 0; nt < 8; nt++) {
            int c = colBase + wn * 64 + nt * 8 + qc;
            float* p = acc[mt][nt];
            __stcs((float2*)&out[(size_t)r0 * NN + c], make_float2(p[0], p[1]));
            __stcs((float2*)&out[(size_t)(r0 + 8) * NN + c], make_float2(p[2], p[3]));
            if (mirror) {
                __stcs(&out[(size_t)c * NN + r0], p[0]);
                __stcs(&out[(size_t)(c + 1) * NN + r0], p[1]);
                __stcs(&out[(size_t)c * NN + r0 + 8], p[2]);
                __stcs(&out[(size_t)(c + 1) * NN + r0 + 8], p[3]);
            }
        }
    }
}

// ---------------- launch ----------------
extern "C" void kernel_launch(void* const* d_in, const int* in_sizes, int n_in,
                              void* d_out, int out_size) {
    const float* features = (const float*)d_in[0];
    const float* W0       = (const float*)d_in[1];
    const float* Wm       = (const float*)d_in[2];
    const float* Ws       = (const float*)d_in[3];
    const float* noise    = (const float*)d_in[4];
    const void*  ei       = d_in[5];
    float*       out      = (float*)d_out;

    static cudaStream_t s2 = nullptr;
    static cudaEvent_t evFork = nullptr, evJoin = nullptr;
    if (s2 == nullptr) {
        cudaStreamCreateWithFlags(&s2, cudaStreamNonBlocking);
        cudaEventCreateWithFlags(&evFork, cudaEventDisableTiming);
        cudaEventCreateWithFlags(&evJoin, cudaEventDisableTiming);
        const int zzt_smem = 2 * 128 * ZS * 2;  // 69632 B
        cudaFuncSetAttribute(k_zzt_mma, cudaFuncAttributeMaxDynamicSharedMemorySize,
                             zzt_smem);
    }
    const int zzt_smem = 2 * 128 * ZS * 2;

    // fork: gemm1 (features@W0, norm-free) is independent of the CSR chain
    cudaEventRecord(evFork, 0);
    cudaStreamWaitEvent(s2, evFork, 0);
    k_gemm_norm<FIN, 0><<<NN / 64, 256, 0, s2>>>(features, W0);
    cudaEventRecord(evJoin, s2);

    // main chain: CSR build (g_deg arrives zeroed — k_scan restored it last call)
    k_init<<<1, 64>>>((const int*)ei);
    k_count<<<(NE / 2 + 255) / 256, 256>>>(ei);
    k_scan<<<1, 1024>>>();
    k_fill<<<(NE / 2 + 255) / 256, 256>>>(ei);

    // join: agg1 needs both g_H1 (s2) and CSR (main chain)
    cudaStreamWaitEvent(0, evJoin, 0);
    k_agg1<<<NN / 8, 256>>>();
    k_gemm_norm<FH, 1><<<NN / 64, 256>>>(Wm, Ws);
    k_agg2z<<<NN / 8, 256>>>(noise);

    k_zzt_mma<<<NTRI, 256, zzt_smem>>>(out);
}

// round 16
// speedup vs baseline: 1.0169x; 1.0169x over previous
#include <cuda_runtime.h>
#include <cuda_bf16.h>
#include <math.h>
#include <stdint.h>

#define NN  12288
#define NE  393216
#define FIN 256
#define FH  128
#define FZ  64
#define KC  128   // stored Z layout: [hi(64) | lo(64)] per row

// ---------------- scratch (no allocs allowed) ----------------
__device__ int   g_deg[NN];          // zero-initialized; k_scan restores zero each call
__device__ float g_norm[NN];
__device__ int   g_rowptr[NN + 1];
__device__ int   g_cursor[NN];
__device__ int   g_csrc[NE];
__device__ float g_H1[NN * FH];
__device__ float g_hidden[NN * FH];
__device__ float g_MS[NN * FH];
__device__ __align__(16) __nv_bfloat16 g_Zc[NN * KC];
__device__ int   g_is64 = 1;

// ---------------- f32x2 packed-FMA helpers (prologue GEMMs) ----------------
__device__ __forceinline__ unsigned long long ffma2(unsigned long long a,
                                                    unsigned long long b,
                                                    unsigned long long c) {
    unsigned long long d;
    asm("fma.rn.f32x2 %0, %1, %2, %3;" : "=l"(d) : "l"(a), "l"(b), "l"(c));
    return d;
}
__device__ __forceinline__ unsigned long long pack2(float x, float y) {
    unsigned long long d;
    asm("mov.b64 %0, {%1, %2};" : "=l"(d) : "f"(x), "f"(y));
    return d;
}
__device__ __forceinline__ float2 unpack2(unsigned long long v) {
    float2 r;
    asm("mov.b64 {%0, %1}, %2;" : "=f"(r.x), "=f"(r.y) : "l"(v));
    return r;
}

__device__ __forceinline__ uint32_t smem_u32(const void* p) {
    uint32_t a;
    asm("{ .reg .u64 t; cvta.to.shared.u64 t, %1; cvt.u32.u64 %0, t; }" : "=r"(a) : "l"(p));
    return a;
}
#define CP_ASYNC16(dst, src) \
    asm volatile("cp.async.cg.shared.global [%0], [%1], 16;" :: "r"(dst), "l"(src))
#define CP_COMMIT() asm volatile("cp.async.commit_group;" ::: "memory")
#define CP_WAIT(n)  asm volatile("cp.async.wait_group %0;" :: "n"(n) : "memory")

// ---------------- init: dtype detect only (deg zeroing lives in k_scan) ----------------
__global__ void k_init(const int* __restrict__ ei32) {
    int nz = (ei32[threadIdx.x * 2 + 1] != 0);
    unsigned m = __ballot_sync(0xffffffffu, nz);
    if (threadIdx.x == 0) g_is64 = (m == 0) ? 1 : 0;
}

__device__ __forceinline__ int load_idx(const void* ei, int pos) {
    if (g_is64) return (int)((const long long*)ei)[pos];
    return ((const int*)ei)[pos];
}

// one edge per thread (latency-bound: maximize warp pool, one atomic per thread)
__global__ void k_count(const void* __restrict__ ei) {
    int e = blockIdx.x * blockDim.x + threadIdx.x;
    if (e < NE) atomicAdd(&g_deg[load_idx(ei, NE + e)], 1);
}

__global__ void k_scan() {
    __shared__ int wsum[32];
    int t = threadIdx.x, lane = t & 31, w = t >> 5;
    int warpBase = w * 384;
    int vals[12], excl[12];
#pragma unroll
    for (int k = 0; k < 12; k++) vals[k] = g_deg[warpBase + k * 32 + lane];
    int run = 0;
#pragma unroll
    for (int k = 0; k < 12; k++) {
        int d = vals[k];
        int v = d;
#pragma unroll
        for (int off = 1; off < 32; off <<= 1) {
            int u = __shfl_up_sync(0xffffffffu, v, off);
            if (lane >= off) v += u;
        }
        excl[k] = run + v - d;
        run += __shfl_sync(0xffffffffu, v, 31);
    }
    if (lane == 0) wsum[w] = run;
    __syncthreads();
    if (w == 0) {
        int x = wsum[lane];
#pragma unroll
        for (int off = 1; off < 32; off <<= 1) {
            int u = __shfl_up_sync(0xffffffffu, x, off);
            if (lane >= off) x += u;
        }
        wsum[lane] = x;
    }
    __syncthreads();
    int base = w ? wsum[w - 1] : 0;
#pragma unroll
    for (int k = 0; k < 12; k++) {
        int idx = warpBase + k * 32 + lane;
        int p = base + excl[k];
        g_rowptr[idx] = p;
        g_cursor[idx] = p;
        int d = vals[k];
        g_norm[idx] = rsqrtf((float)(d > 1 ? d : 1));
        g_deg[idx] = 0;  // restore invariant for the next graph replay
    }
    if (t == 1023) g_rowptr[NN] = wsum[31];
}

// one edge per thread
__global__ void k_fill(const void* __restrict__ ei) {
    int e = blockIdx.x * blockDim.x + threadIdx.x;
    if (e < NE) {
        int d = load_idx(ei, NE + e);
        int pos = atomicAdd(&g_cursor[d], 1);
        g_csrc[pos] = load_idx(ei, e);
    }
}

// ---------------- dense GEMM [M,K] x [K,128], FFMA2 ----------------
// MODE 0: C = Ain@Bin (norm folded into k_agg1; independent of CSR chain).
// MODE 1: C = (g_hidden@[Wm|Ws])*norm[row]; Ain=Wm, Bin=Ws read directly.
template <int K, int MODE>
__global__ void __launch_bounds__(256) k_gemm_norm(const float* __restrict__ Ain,
                                                   const float* __restrict__ Bin) {
    __shared__ float As[32][68];
    __shared__ float Bs[32][132];
    const float* A = (MODE == 0) ? Ain : g_hidden;
    float*       C = (MODE == 0) ? g_H1 : g_MS;

    int tid = threadIdx.x;
    int tx = tid & 15, ty = tid >> 4;
    int rowBase = blockIdx.x * 64;

    unsigned long long acc2[4][4];
#pragma unroll
    for (int i = 0; i < 4; i++)
#pragma unroll
        for (int q = 0; q < 4; q++) acc2[i][q] = 0ULL;

    for (int kc = 0; kc < K; kc += 32) {
#pragma unroll
        for (int i = 0; i < 2; i++) {
            int slot = tid + i * 256;
            int r = slot >> 3, c4 = slot & 7;
            float4 v = *(const float4*)&A[(size_t)(rowBase + r) * K + kc + c4 * 4];
            As[c4 * 4 + 0][r] = v.x; As[c4 * 4 + 1][r] = v.y;
            As[c4 * 4 + 2][r] = v.z; As[c4 * 4 + 3][r] = v.w;
        }
#pragma unroll
        for (int i = 0; i < 4; i++) {
            int slot = tid + i * 256;
            int r = slot >> 5, c4 = slot & 31;
            if (MODE == 0) {
                *(float4*)&Bs[r][c4 * 4] = *(const float4*)&Bin[(kc + r) * 128 + c4 * 4];
            } else {
                const float* srcp = (c4 < 16) ? Ain : Bin;
                int jj = (c4 & 15) * 4;
                *(float4*)&Bs[r][c4 * 4] = *(const float4*)&srcp[(kc + r) * 64 + jj];
            }
        }
        __syncthreads();
#pragma unroll
        for (int k = 0; k < 32; k++) {
            float4 av = *(const float4*)&As[k][ty * 4];
            unsigned long long a2[4];
            a2[0] = pack2(av.x, av.x); a2[1] = pack2(av.y, av.y);
            a2[2] = pack2(av.z, av.z); a2[3] = pack2(av.w, av.w);
            unsigned long long b2[4];
#pragma unroll
            for (int q = 0; q < 4; q++)
                b2[q] = *(const unsigned long long*)&Bs[k][tx * 8 + 2 * q];
#pragma unroll
            for (int i = 0; i < 4; i++)
#pragma unroll
                for (int q = 0; q < 4; q++) acc2[i][q] = ffma2(a2[i], b2[q], acc2[i][q]);
        }
        __syncthreads();
    }
#pragma unroll
    for (int i = 0; i < 4; i++) {
        int r = rowBase + ty * 4 + i;
        float nm = (MODE == 0) ? 1.0f : g_norm[r];
        float o[8];
#pragma unroll
        for (int q = 0; q < 4; q++) {
            float2 f = unpack2(acc2[i][q]);
            o[2 * q] = f.x * nm;
            o[2 * q + 1] = f.y * nm;
        }
        float* op = &C[(size_t)r * 128 + tx * 8];
        *(float4*)&op[0] = make_float4(o[0], o[1], o[2], o[3]);
        *(float4*)&op[4] = make_float4(o[4], o[5], o[6], o[7]);
    }
}

// ---------------- gather aggregation (warp per node) ----------------
// acc += H1[src] * norm[src], 4 independent chains for MLP
__global__ void k_agg1() {
    int gw = (blockIdx.x * blockDim.x + threadIdx.x) >> 5;
    if (gw >= NN) return;
    int lane = threadIdx.x & 31;
    int s0 = g_rowptr[gw], s1 = g_rowptr[gw + 1];
    float4 ac0 = make_float4(0.f, 0.f, 0.f, 0.f);
    float4 ac1 = make_float4(0.f, 0.f, 0.f, 0.f);
    float4 ac2 = make_float4(0.f, 0.f, 0.f, 0.f);
    float4 ac3 = make_float4(0.f, 0.f, 0.f, 0.f);
    int e = s0;
    for (; e + 3 < s1; e += 4) {
        int a = g_csrc[e], b = g_csrc[e + 1], c = g_csrc[e + 2], d = g_csrc[e + 3];
        float na = g_norm[a], nb = g_norm[b], nc = g_norm[c], nd = g_norm[d];
        float4 va = *(const float4*)&g_H1[(size_t)a * FH + lane * 4];
        float4 vb = *(const float4*)&g_H1[(size_t)b * FH + lane * 4];
        float4 vc = *(const float4*)&g_H1[(size_t)c * FH + lane * 4];
        float4 vd = *(const float4*)&g_H1[(size_t)d * FH + lane * 4];
        ac0.x = fmaf(va.x, na, ac0.x); ac0.y = fmaf(va.y, na, ac0.y);
        ac0.z = fmaf(va.z, na, ac0.z); ac0.w = fmaf(va.w, na, ac0.w);
        ac1.x = fmaf(vb.x, nb, ac1.x); ac1.y = fmaf(vb.y, nb, ac1.y);
        ac1.z = fmaf(vb.z, nb, ac1.z); ac1.w = fmaf(vb.w, nb, ac1.w);
        ac2.x = fmaf(vc.x, nc, ac2.x); ac2.y = fmaf(vc.y, nc, ac2.y);
        ac2.z = fmaf(vc.z, nc, ac2.z); ac2.w = fmaf(vc.w, nc, ac2.w);
        ac3.x = fmaf(vd.x, nd, ac3.x); ac3.y = fmaf(vd.y, nd, ac3.y);
        ac3.z = fmaf(vd.z, nd, ac3.z); ac3.w = fmaf(vd.w, nd, ac3.w);
    }
    for (; e < s1; e++) {
        int a = g_csrc[e];
        float na = g_norm[a];
        float4 va = *(const float4*)&g_H1[(size_t)a * FH + lane * 4];
        ac0.x = fmaf(va.x, na, ac0.x); ac0.y = fmaf(va.y, na, ac0.y);
        ac0.z = fmaf(va.z, na, ac0.z); ac0.w = fmaf(va.w, na, ac0.w);
    }
    float nm = g_norm[gw];
    *(float4*)&g_hidden[(size_t)gw * FH + lane * 4] =
        make_float4((ac0.x + ac1.x + ac2.x + ac3.x) * nm,
                    (ac0.y + ac1.y + ac2.y + ac3.y) * nm,
                    (ac0.z + ac1.z + ac2.z + ac3.z) * nm,
                    (ac0.w + ac1.w + ac2.w + ac3.w) * nm);
}

// aggregate MS, post-norm, relu, reparameterize, emit [hi|lo] bf16 rows
__global__ void k_agg2z(const float* __restrict__ noise) {
    __shared__ float sm[8][128];
    int wl = threadIdx.x >> 5;
    int gw = (blockIdx.x * blockDim.x + threadIdx.x) >> 5;
    if (gw >= NN) return;
    int lane = threadIdx.x & 31;
    int s0 = g_rowptr[gw], s1 = g_rowptr[gw + 1];
    float4 ac0 = make_float4(0.f, 0.f, 0.f, 0.f);
    float4 ac1 = make_float4(0.f, 0.f, 0.f, 0.f);
    int e = s0;
    for (; e + 3 < s1; e += 4) {
        int a = g_csrc[e], b = g_csrc[e + 1], c = g_csrc[e + 2], d = g_csrc[e + 3];
        float4 va = *(const float4*)&g_MS[(size_t)a * FH + lane * 4];
        float4 vb = *(const float4*)&g_MS[(size_t)b * FH + lane * 4];
        float4 vc = *(const float4*)&g_MS[(size_t)c * FH + lane * 4];
        float4 vd = *(const float4*)&g_MS[(size_t)d * FH + lane * 4];
        ac0.x += va.x + vb.x; ac0.y += va.y + vb.y;
        ac0.z += va.z + vb.z; ac0.w += va.w + vb.w;
        ac1.x += vc.x + vd.x; ac1.y += vc.y + vd.y;
        ac1.z += vc.z + vd.z; ac1.w += vc.w + vd.w;
    }
    for (; e < s1; e++) {
        int a = g_csrc[e];
        float4 va = *(const float4*)&g_MS[(size_t)a * FH + lane * 4];
        ac0.x += va.x; ac0.y += va.y; ac0.z += va.z; ac0.w += va.w;
    }
    float nm = g_norm[gw];
    sm[wl][lane * 4 + 0] = fmaxf((ac0.x + ac1.x) * nm, 0.f);
    sm[wl][lane * 4 + 1] = fmaxf((ac0.y + ac1.y) * nm, 0.f);
    sm[wl][lane * 4 + 2] = fmaxf((ac0.z + ac1.z) * nm, 0.f);
    sm[wl][lane * 4 + 3] = fmaxf((ac0.w + ac1.w) * nm, 0.f);
    __syncwarp();
    if (lane < 16) {
        int j = lane * 4;
        float4 nz = *(const float4*)&noise[(size_t)gw * FZ + j];
        float z[4];
        z[0] = fmaf(nz.x, expf(sm[wl][64 + j + 0]), sm[wl][j + 0]);
        z[1] = fmaf(nz.y, expf(sm[wl][64 + j + 1]), sm[wl][j + 1]);
        z[2] = fmaf(nz.z, expf(sm[wl][64 + j + 2]), sm[wl][j + 2]);
        z[3] = fmaf(nz.w, expf(sm[wl][64 + j + 3]), sm[wl][j + 3]);
        __nv_bfloat16 hi[4], lo[4];
#pragma unroll
        for (int q = 0; q < 4; q++) {
            hi[q] = __float2bfloat16(z[q]);
            lo[q] = __float2bfloat16(z[q] - __bfloat162float(hi[q]));
        }
        *(__nv_bfloat162*)&g_Zc[(size_t)gw * KC + j]          = *(__nv_bfloat162*)&hi[0];
        *(__nv_bfloat162*)&g_Zc[(size_t)gw * KC + j + 2]      = *(__nv_bfloat162*)&hi[2];
        *(__nv_bfloat162*)&g_Zc[(size_t)gw * KC + 64 + j]     = *(__nv_bfloat162*)&lo[0];
        *(__nv_bfloat162*)&g_Zc[(size_t)gw * KC + 64 + j + 2] = *(__nv_bfloat162*)&lo[2];
    }
}

// ---------------- Z @ Z^T via mma.sync bf16, split-precision (R12 structure) ----------------
#define ZS 136     // padded smem row stride in bf16 (272 B)
#define NTRI 4656  // 96*97/2 upper-triangle tiles

__device__ __forceinline__ void ldsm_x4(uint32_t addr, uint32_t& r0, uint32_t& r1,
                                        uint32_t& r2, uint32_t& r3) {
    asm volatile("ldmatrix.sync.aligned.m8n8.x4.shared.b16 {%0,%1,%2,%3}, [%4];"
                 : "=r"(r0), "=r"(r1), "=r"(r2), "=r"(r3) : "r"(addr));
}
__device__ __forceinline__ void mma16816(float* d, uint32_t a0, uint32_t a1,
                                         uint32_t a2, uint32_t a3, uint32_t b0,
                                         uint32_t b1) {
    asm volatile(
        "mma.sync.aligned.m16n8k16.row.col.f32.bf16.bf16.f32 "
        "{%0,%1,%2,%3}, {%4,%5,%6,%7}, {%8,%9}, {%0,%1,%2,%3};"
        : "+f"(d[0]), "+f"(d[1]), "+f"(d[2]), "+f"(d[3])
        : "r"(a0), "r"(a1), "r"(a2), "r"(a3), "r"(b0), "r"(b1));
}

__global__ void __launch_bounds__(256, 2) k_zzt_mma(float* __restrict__ out) {
    // triangular decode: row by has (96 - by) tiles, bx in [by, 96)
    int t = blockIdx.x;
    int by = (int)((193.0f - sqrtf(fmaf(-8.0f, (float)t, 193.0f * 193.0f))) * 0.5f);
    while (by * 96 - (by * (by - 1)) / 2 > t) by--;
    while ((by + 1) * 96 - ((by + 1) * by) / 2 <= t) by++;
    const int bx = by + (t - (by * 96 - (by * (by - 1)) / 2));

    extern __shared__ __nv_bfloat16 zs[];  // A: [128][ZS], B: [128][ZS]
    __nv_bfloat16* As = zs;
    __nv_bfloat16* Bs = zs + 128 * ZS;
    const int tid = threadIdx.x;
    const int lane = tid & 31, wid = tid >> 5;
    const int wm = wid & 3, wn = wid >> 2;
    const int rowBase = by * 128;
    const int colBase = bx * 128;

    // group 0: hi halves of A and B
    {
        int tile = tid >> 7, r = tid & 127;
        int grow = (tile ? colBase : rowBase) + r;
        const char* src = (const char*)&g_Zc[(size_t)grow * KC];
        uint32_t dst = smem_u32((tile ? Bs : As) + r * ZS);
#pragma unroll
        for (int i = 0; i < 8; i++) CP_ASYNC16(dst + i * 16, src + i * 16);
    }
    CP_COMMIT();
    // group 1: B.lo
    {
        int r = tid >> 1, h = (tid & 1) * 64;
        const char* src = (const char*)&g_Zc[(size_t)(colBase + r) * KC] + 128 + h;
        uint32_t dst = smem_u32(Bs + r * ZS) + 128 + h;
#pragma unroll
        for (int i = 0; i < 4; i++) CP_ASYNC16(dst + i * 16, src + i * 16);
    }
    CP_COMMIT();
    // group 2: A.lo
    {
        int r = tid >> 1, h = (tid & 1) * 64;
        const char* src = (const char*)&g_Zc[(size_t)(rowBase + r) * KC] + 128 + h;
        uint32_t dst = smem_u32(As + r * ZS) + 128 + h;
#pragma unroll
        for (int i = 0; i < 4; i++) CP_ASYNC16(dst + i * 16, src + i * 16);
    }
    CP_COMMIT();

    uint32_t aBase = smem_u32(As);
    uint32_t bBase = smem_u32(Bs);
    const int lr = lane & 15, lc = (lane >> 4) * 8;

    float acc[2][8][4];
#pragma unroll
    for (int mt = 0; mt < 2; mt++)
#pragma unroll
        for (int nt = 0; nt < 8; nt++)
#pragma unroll
            for (int q = 0; q < 4; q++) acc[mt][nt][q] = 0.f;

    const int ks_a[12] = {0, 1, 2, 3, 0, 1, 2, 3, 4, 5, 6, 7};
    const int ks_b[12] = {0, 1, 2, 3, 4, 5, 6, 7, 0, 1, 2, 3};

    CP_WAIT(2);
    __syncthreads();

#pragma unroll
    for (int ks = 0; ks < 12; ks++) {
        if (ks == 4) { CP_WAIT(1); __syncthreads(); }
        if (ks == 8) { CP_WAIT(0); __syncthreads(); }
        const int ka = ks_a[ks] * 16, kb = ks_b[ks] * 16;
        uint32_t a[2][4];
#pragma unroll
        for (int mt = 0; mt < 2; mt++) {
            uint32_t ad = aBase + ((wm * 32 + mt * 16 + lr) * ZS + ka + lc) * 2;
            ldsm_x4(ad, a[mt][0], a[mt][1], a[mt][2], a[mt][3]);
        }
        uint32_t b[8][2];
#pragma unroll
        for (int np = 0; np < 4; np++) {
            uint32_t bd = bBase + ((wn * 64 + np * 16 + lr) * ZS + kb + lc) * 2;
            uint32_t r0, r1, r2, r3;
            ldsm_x4(bd, r0, r1, r2, r3);
            b[2 * np][0] = r0; b[2 * np][1] = r2;
            b[2 * np + 1][0] = r1; b[2 * np + 1][1] = r3;
        }
#pragma unroll
        for (int mt = 0; mt < 2; mt++)
#pragma unroll
            for (int nt = 0; nt < 8; nt++)
                mma16816(acc[mt][nt], a[mt][0], a[mt][1], a[mt][2], a[mt][3],
                         b[nt][0], b[nt][1]);
    }

    // Epilogue: streaming stores (write-once output; keep L2 for operands).
    const int qr = lane >> 2, qc = (lane & 3) * 2;
    const bool mirror = (bx != by);
#pragma unroll
    for (int mt = 0; mt < 2; mt++) {
        int r0 = rowBase + wm * 32 + mt * 16 + qr;
#pragma unroll
        for (int nt = 0; nt < 8; nt++) {
            int c = colBase + wn * 64 + nt * 8 + qc;
            float* p = acc[mt][nt];
            __stcs((float2*)&out[(size_t)r0 * NN + c], make_float2(p[0], p[1]));
            __stcs((float2*)&out[(size_t)(r0 + 8) * NN + c], make_float2(p[2], p[3]));
            if (mirror) {
                __stcs(&out[(size_t)c * NN + r0], p[0]);
                __stcs(&out[(size_t)(c + 1) * NN + r0], p[1]);
                __stcs(&out[(size_t)c * NN + r0 + 8], p[2]);
                __stcs(&out[(size_t)(c + 1) * NN + r0 + 8], p[3]);
            }
        }
    }
}

// ---------------- launch ----------------
extern "C" void kernel_launch(void* const* d_in, const int* in_sizes, int n_in,
                              void* d_out, int out_size) {
    const float* features = (const float*)d_in[0];
    const float* W0       = (const float*)d_in[1];
    const float* Wm       = (const float*)d_in[2];
    const float* Ws       = (const float*)d_in[3];
    const float* noise    = (const float*)d_in[4];
    const void*  ei       = d_in[5];
    float*       out      = (float*)d_out;

    static cudaStream_t s2 = nullptr;
    static cudaEvent_t evFork = nullptr, evJoin = nullptr;
    if (s2 == nullptr) {
        cudaStreamCreateWithFlags(&s2, cudaStreamNonBlocking);
        cudaEventCreateWithFlags(&evFork, cudaEventDisableTiming);
        cudaEventCreateWithFlags(&evJoin, cudaEventDisableTiming);
        const int zzt_smem = 2 * 128 * ZS * 2;  // 69632 B
        cudaFuncSetAttribute(k_zzt_mma, cudaFuncAttributeMaxDynamicSharedMemorySize,
                             zzt_smem);
    }
    const int zzt_smem = 2 * 128 * ZS * 2;

    // fork: gemm1 (features@W0, norm-free) is independent of the CSR chain
    cudaEventRecord(evFork, 0);
    cudaStreamWaitEvent(s2, evFork, 0);
    k_gemm_norm<FIN, 0><<<NN / 64, 256, 0, s2>>>(features, W0);
    cudaEventRecord(evJoin, s2);

    // main chain: CSR build (g_deg arrives zeroed — k_scan restored it last call)
    k_init<<<1, 64>>>((const int*)ei);
    k_count<<<(NE + 255) / 256, 256>>>(ei);
    k_scan<<<1, 1024>>>();
    k_fill<<<(NE + 255) / 256, 256>>>(ei);

    // join: agg1 needs both g_H1 (s2) and CSR (main chain)
    cudaStreamWaitEvent(0, evJoin, 0);
    k_agg1<<<NN / 8, 256>>>();
    k_gemm_norm<FH, 1><<<NN / 64, 256>>>(Wm, Ws);
    k_agg2z<<<NN / 8, 256>>>(noise);

    k_zzt_mma<<<NTRI, 256, zzt_smem>>>(out);
}